// round 15
// baseline (speedup 1.0000x reference)
#include <cuda_runtime.h>
#include <cstdint>

#define HH 512
#define WW 512
#define WORDS 16
#define UROWS 32                        // a-rows per unit
#define NLOADMAX 35                     // rows loaded by chain-last unit
#define NTH 512
#define NWARPS 16
#define NOFF 12
#define NB 128
#define UNITS_PER_IMG (HH / UROWS)      // 16
#define NBLK 148
#define SLOTF (NLOADMAX * WW)           // 17920 floats = 71680 B
#define BITSW 576                       // 35*16 = 560 words + guard + pad
#define TICKETS (UNITS_PER_IMG * NWARPS)  // 256 warp-completions per image

// zero-initialized; reset after each use -> deterministic graph replays
__device__ int g_cnt[NB * NOFF * 2];
__device__ unsigned g_arrive[NB];

__device__ __forceinline__ void mbar_init(unsigned a, unsigned cnt) {
    asm volatile("mbarrier.init.shared.b64 [%0], %1;" :: "r"(a), "r"(cnt) : "memory");
}
__device__ __forceinline__ void mbar_expect_tx(unsigned a, unsigned bytes) {
    asm volatile("mbarrier.arrive.expect_tx.shared.b64 _, [%0], %1;"
                 :: "r"(a), "r"(bytes) : "memory");
}
__device__ __forceinline__ void bulk_g2s(unsigned dst, const float* src,
                                         unsigned bytes, unsigned mbar) {
    asm volatile("cp.async.bulk.shared::cluster.global.mbarrier::complete_tx::bytes "
                 "[%0], [%1], %2, [%3];"
                 :: "r"(dst), "l"(src), "r"(bytes), "r"(mbar) : "memory");
}
__device__ __forceinline__ void mbar_wait(unsigned a, unsigned parity) {
    asm volatile(
        "{\n\t"
        ".reg .pred P1;\n\t"
        "WAIT_LOOP_%=:\n\t"
        "mbarrier.try_wait.parity.shared.b64 P1, [%0], %1;\n\t"
        "@P1 bra.uni WAIT_DONE_%=;\n\t"
        "bra.uni WAIT_LOOP_%=;\n\t"
        "WAIT_DONE_%=:\n\t"
        "}"
        :: "r"(a), "r"(parity) : "memory");
}

// evaluate all 12 offsets for bit-word (r, w) within one unit's bit slot
__device__ __forceinline__ void eval12(const unsigned* __restrict__ bits,
                                       int r, int w,
                                       const int* __restrict__ rl,
                                       unsigned* __restrict__ acc)
{
    constexpr int RS[NOFF] = {0, 1, 1, 1, 0, 2, 2, 2, 0, 3, 3, 3};
    constexpr int CS[NOFF] = {1, 1, 0, -1, 2, 2, 0, -2, 3, 3, 0, -3};
    const bool firstw = (w == 0);
    const bool lastw  = (w == WORDS - 1);
    const int i = r * WORDS + w;
    const unsigned A = bits[i];

    #pragma unroll
    for (int o = 0; o < NOFF; ++o) {
        const int R = RS[o];
        const int C = CS[o];
        const int bi = i + R * WORDS;
        unsigned B;
        if (C > 0)       B = __funnelshift_r(bits[bi], bits[bi + 1], C);
        else if (C < 0)  B = __funnelshift_l(bits[bi - 1], bits[bi], -C);
        else             B = bits[bi];

        unsigned m = 0xffffffffu;
        if (C > 0 && lastw)  m = 0xffffffffu >> C;
        if (C < 0 && firstw) m = 0xffffffffu << (-C);
        if (r >= rl[R]) m = 0u;              // image-last row clip

        acc[o] += (unsigned)(__popc((A ^ B) & m) << 16)
                |  (unsigned)__popc((A & B) & m);
    }
}

// count one unit (this thread's single word), flush to g_cnt, ticket, finalize
__device__ __forceinline__ void count_flush(const unsigned* __restrict__ bt,
                                            int u, float* __restrict__ out,
                                            int tid, int lane)
{
    constexpr int RS[NOFF] = {0, 1, 1, 1, 0, 2, 2, 2, 0, 3, 3, 3};
    constexpr int CS[NOFF] = {1, 1, 0, -1, 2, 2, 0, -2, 3, 3, 0, -3};

    const int img  = u >> 4;
    const int row0 = (u & 15) * UROWS;

    int rl[4];
    #pragma unroll
    for (int R = 0; R < 4; ++R) rl[R] = min(UROWS, HH - R - row0);

    unsigned acc[NOFF];
    #pragma unroll
    for (int o = 0; o < NOFF; ++o) acc[o] = 0;

    eval12(bt, tid >> 4, tid & 15, rl, acc);   // 512 threads x 512 words

    // warp-reduce each offset; lane0 flushes (REDG, no return)
    #pragma unroll
    for (int o = 0; o < NOFF; ++o) {
        unsigned v = __reduce_add_sync(0xffffffffu, acc[o]);
        if (lane == 0) {
            atomicAdd(&g_cnt[(img * NOFF + o) * 2 + 0], (int)(v >> 16));
            atomicAdd(&g_cnt[(img * NOFF + o) * 2 + 1], (int)(v & 0xffffu));
        }
    }

    // warp-local ticket: 256 warp-completions per image; last warp finalizes
    unsigned t = 0u;
    if (lane == 0) {
        __threadfence();                      // release flushes before ticket
        t = atomicAdd(&g_arrive[img], 1u);
    }
    t = __shfl_sync(0xffffffffu, t, 0);
    if (t == TICKETS - 1) {
        if (lane == 0) atomicExch(&g_arrive[img], 0u);
        __threadfence();                      // acquire before reading g_cnt
        if (lane < NOFF) {
            const int idx  = img * NOFF + lane;
            const int diff = atomicExch(&g_cnt[idx * 2 + 0], 0);
            const int n11  = atomicExch(&g_cnt[idx * 2 + 1], 0);

            const int R  = RS[lane];
            const int Ca = CS[lane] < 0 ? -CS[lane] : CS[lane];
            const int N  = (HH - R) * (WW - Ca);
            const int n00 = N - n11 - diff;

            const float inv = 1.0f / (float)(2 * N - 4 * n00);
            float* o = out + (size_t)img * (NOFF * 4) + lane * 4;
            o[0] = (float)(4 * n00) * inv;
            const float v1 = (float)(2 * diff - 4 * n00) * inv;
            o[1] = v1;
            o[2] = v1;
            o[3] = (float)(2 * (N - 2 * diff)) * inv;
        }
    }
}

extern __shared__ unsigned char dynsmem[];

__global__ __launch_bounds__(NTH, 1)
void glcm_chain(const float* __restrict__ in, float* __restrict__ out)
{
    float*    sbuf = reinterpret_cast<float*>(dynsmem);               // 3 slots
    unsigned* bits = reinterpret_cast<unsigned*>(dynsmem + 3 * SLOTF * 4);
    __shared__ unsigned long long s_mbar[3];

    const int tid  = threadIdx.x;
    const int lane = tid & 31;
    const int warp = tid >> 5;
    const int b    = blockIdx.x;

    // contiguous unit chain: 2048 = 124*14 + 24*13
    int u0, n;
    if (b < 124) { u0 = b * 14;                n = 14; }
    else         { u0 = 1736 + (b - 124) * 13; n = 13; }

    const unsigned sb  = (unsigned)__cvta_generic_to_shared(sbuf);
    const unsigned mb0 = (unsigned)__cvta_generic_to_shared(&s_mbar[0]);

    // unit -> gmem row pointer / rows to load for chain index j
    auto usrc = [&](int u) {
        return in + ((size_t)(u >> 4) * HH + (u & 15) * UROWS) * WW;
    };
    auto unload = [&](int j) {
        const int u = u0 + j;
        return (j == n - 1) ? min(NLOADMAX, HH - (u & 15) * UROWS) : UROWS;
    };

    if (tid == 0) {
        #pragma unroll
        for (int s = 0; s < 3; ++s) mbar_init(mb0 + 8u * s, 1u);
        // prime units 0 and 1
        mbar_expect_tx(mb0, (unsigned)unload(0) * WW * 4);
        bulk_g2s(sb, usrc(u0), (unsigned)unload(0) * WW * 4, mb0);
        if (n > 1) {
            mbar_expect_tx(mb0 + 8u, (unsigned)unload(1) * WW * 4);
            bulk_g2s(sb + SLOTF * 4, usrc(u0 + 1),
                     (unsigned)unload(1) * WW * 4, mb0 + 8u);
        }
    }
    __syncthreads();

    for (int j = 0; j < n; ++j) {
        const int slot = j % 3;
        mbar_wait(mb0 + 8u * slot, (unsigned)((j / 3) & 1));

        // ---- pack unit j; rows 0..2 also into previous unit's bit slot -----
        const float* buf = sbuf + slot * SLOTF;
        unsigned* bt     = bits + slot * BITSW;
        unsigned* btprev = bits + ((j + 2) % 3) * BITSW;   // == (j-1)%3
        const int nload  = unload(j);

        for (int r = warp; r < nload; r += NWARPS) {
            const float* rp = buf + r * WW;
            unsigned b4[4];
            #pragma unroll
            for (int w = 0; w < WORDS; ++w) {
                float v = rp[w * 32 + lane];
                b4[w & 3] = __ballot_sync(0xffffffffu, v > 0.0f);
                if ((w & 3) == 3 && lane == 0) {
                    uint4 q = make_uint4(b4[0], b4[1], b4[2], b4[3]);
                    *reinterpret_cast<uint4*>(&bt[r * WORDS + (w - 3)]) = q;
                    if (j > 0 && r < 3)        // halo for count(j-1)
                        *reinterpret_cast<uint4*>(
                            &btprev[(UROWS + r) * WORDS + (w - 3)]) = q;
                }
            }
        }
        __syncthreads();                       // the ONE sync per unit

        // ---- keep 2 bulks in flight: issue unit j+2 ------------------------
        if (tid == 0 && j + 2 < n) {
            const int s2 = (j + 2) % 3;
            const unsigned bytes = (unsigned)unload(j + 2) * WW * 4;
            mbar_expect_tx(mb0 + 8u * s2, bytes);
            bulk_g2s(sb + s2 * SLOTF * 4, usrc(u0 + j + 2), bytes, mb0 + 8u * s2);
        }

        // ---- count unit j-1 (its +3-row halo just landed via pack(j)) ------
        if (j > 0)
            count_flush(btprev, u0 + j - 1, out, tid, lane);
    }

    // epilogue: chain-last unit (rows 32..34 self-loaded or image-clipped)
    count_flush(bits + ((n - 1) % 3) * BITSW, u0 + n - 1, out, tid, lane);
}

extern "C" void kernel_launch(void* const* d_in, const int* in_sizes, int n_in,
                              void* d_out, int out_size)
{
    (void)n_in; (void)out_size; (void)in_sizes;
    const int smem = 3 * SLOTF * 4 + 3 * BITSW * 4;   // 215040 + 6912 = 221952 B
    cudaFuncSetAttribute(glcm_chain, cudaFuncAttributeMaxDynamicSharedMemorySize, smem);
    glcm_chain<<<NBLK, NTH, smem>>>((const float*)d_in[0], (float*)d_out);
}

// round 16
// speedup vs baseline: 1.7469x; 1.7469x over previous
#include <cuda_runtime.h>
#include <cstdint>

#define HH 512
#define WW 512
#define WORDS 16
#define SLAB 128
#define HALO 3
#define NTH 544                         // 16 consumer warps + 1 producer warp
#define NCONS 512
#define NOFF 12
#define SLABS (HH / SLAB)               // 4
#define MAXB 128
#define CROWS 16                        // rows per TMA chunk
#define NCHUNK (SLAB / CROWS)           // 8
#define CFLOATS (CROWS * WW)            // 8192 floats = 32KB
#define CBYTES (CFLOATS * 4)
#define NSTAGE 2
#define BITS_WORDS ((SLAB + HALO) * WORDS + WORDS)   // 2112

// zero-initialized; every use paired with a reset -> deterministic graph replays
__device__ int g_cnt[MAXB * NOFF * 2];
__device__ unsigned g_arrive[MAXB];

__device__ __forceinline__ void mbar_init(unsigned a, unsigned cnt) {
    asm volatile("mbarrier.init.shared.b64 [%0], %1;" :: "r"(a), "r"(cnt) : "memory");
}
__device__ __forceinline__ void mbar_expect_tx(unsigned a, unsigned bytes) {
    asm volatile("mbarrier.arrive.expect_tx.shared.b64 _, [%0], %1;"
                 :: "r"(a), "r"(bytes) : "memory");
}
__device__ __forceinline__ void mbar_arrive(unsigned a) {
    asm volatile("mbarrier.arrive.shared.b64 _, [%0];" :: "r"(a) : "memory");
}
__device__ __forceinline__ void bulk_g2s(unsigned dst, const float* src,
                                         unsigned bytes, unsigned mbar) {
    asm volatile("cp.async.bulk.shared::cluster.global.mbarrier::complete_tx::bytes "
                 "[%0], [%1], %2, [%3];"
                 :: "r"(dst), "l"(src), "r"(bytes), "r"(mbar) : "memory");
}
__device__ __forceinline__ void mbar_wait(unsigned a, unsigned parity) {
    asm volatile(
        "{\n\t"
        ".reg .pred P1;\n\t"
        "WAIT_LOOP_%=:\n\t"
        "mbarrier.try_wait.parity.shared.b64 P1, [%0], %1;\n\t"
        "@P1 bra.uni WAIT_DONE_%=;\n\t"
        "bra.uni WAIT_LOOP_%=;\n\t"
        "WAIT_DONE_%=:\n\t"
        "}"
        :: "r"(a), "r"(parity) : "memory");
}

// evaluate all 12 offsets for bit-word (r, w)
__device__ __forceinline__ void eval12(const unsigned* __restrict__ bits,
                                       int r, int w,
                                       const int* __restrict__ rl,
                                       unsigned* __restrict__ acc)
{
    constexpr int RS[NOFF] = {0, 1, 1, 1, 0, 2, 2, 2, 0, 3, 3, 3};
    constexpr int CS[NOFF] = {1, 1, 0, -1, 2, 2, 0, -2, 3, 3, 0, -3};
    const bool firstw = (w == 0);
    const bool lastw  = (w == WORDS - 1);
    const int i = r * WORDS + w;
    const unsigned A = bits[i];

    #pragma unroll
    for (int o = 0; o < NOFF; ++o) {
        const int R = RS[o];
        const int C = CS[o];
        const int bi = i + R * WORDS;
        unsigned B;
        if (C > 0)       B = __funnelshift_r(bits[bi], bits[bi + 1], C);
        else if (C < 0)  B = __funnelshift_l(bits[bi - 1], bits[bi], -C);
        else             B = bits[bi];

        unsigned m = 0xffffffffu;
        if (C > 0 && lastw)  m = 0xffffffffu >> C;
        if (C < 0 && firstw) m = 0xffffffffu << (-C);
        if (r >= rl[R]) m = 0u;              // row clip (masks uninit halo too)

        acc[o] += (unsigned)(__popc((A ^ B) & m) << 16)
                |  (unsigned)__popc((A & B) & m);
    }
}

extern __shared__ unsigned char dynsmem[];

__global__ __launch_bounds__(NTH, 3)
void glcm_ws(const float* __restrict__ in, float* __restrict__ out)
{
    constexpr int RS[NOFF] = {0, 1, 1, 1, 0, 2, 2, 2, 0, 3, 3, 3};
    constexpr int CS[NOFF] = {1, 1, 0, -1, 2, 2, 0, -2, 3, 3, 0, -3};

    float*    sbuf = reinterpret_cast<float*>(dynsmem);          // 2 x 32KB
    unsigned* bits = reinterpret_cast<unsigned*>(dynsmem + NSTAGE * CBYTES);
    __shared__ unsigned long long s_full[NSTAGE];
    __shared__ unsigned long long s_empty[NSTAGE];
    __shared__ int s_diff[NOFF];
    __shared__ int s_n11[NOFF];
    __shared__ int s_last;

    const int tid  = threadIdx.x;
    const int lane = tid & 31;
    const int warp = tid >> 5;
    const int r0   = blockIdx.x * SLAB;
    const int b    = blockIdx.y;
    const float* img = in + ((size_t)b * HH + r0) * WW;

    const unsigned sb  = (unsigned)__cvta_generic_to_shared(sbuf);
    const unsigned fu0 = (unsigned)__cvta_generic_to_shared(&s_full[0]);
    const unsigned em0 = (unsigned)__cvta_generic_to_shared(&s_empty[0]);

    if (tid < NOFF) { s_diff[tid] = 0; s_n11[tid] = 0; }
    if (tid == 0) {
        #pragma unroll
        for (int s = 0; s < NSTAGE; ++s) {
            mbar_init(fu0 + 8u * s, 1u);     // tx-based
            mbar_init(em0 + 8u * s, 1u);     // one arrive (tid 0) per use
        }
    }
    __syncthreads();

    if (warp == 16) {
        // ---------------- producer warp: keep the TMA ring full -------------
        if (lane == 0) {
            #pragma unroll 1
            for (int k = 0; k < NCHUNK; ++k) {
                const int s = k & 1;
                if (k >= NSTAGE)
                    mbar_wait(em0 + 8u * s, (unsigned)(((k >> 1) + 1) & 1));
                mbar_expect_tx(fu0 + 8u * s, CBYTES);
                bulk_g2s(sb + s * CBYTES, img + k * CFLOATS, CBYTES, fu0 + 8u * s);
            }
        }
    } else {
        // ---------------- consumers: pack + incremental count ---------------
        // halo rows 128..130 via plain LDG (overlaps chunk-0 TMA flight)
        if (warp < HALO && r0 + SLAB < HH) {
            const float* rp = img + (SLAB + warp) * WW + lane;
            unsigned b4[4];
            #pragma unroll
            for (int w = 0; w < WORDS; ++w) {
                float v = rp[w * 32];
                b4[w & 3] = __ballot_sync(0xffffffffu, v > 0.0f);
                if ((w & 3) == 3 && lane == 0)
                    *reinterpret_cast<uint4*>(&bits[(SLAB + warp) * WORDS + (w - 3)])
                        = make_uint4(b4[0], b4[1], b4[2], b4[3]);
            }
        }

        int rl[4];
        #pragma unroll
        for (int R = 0; R < 4; ++R) rl[R] = min(SLAB, HH - R - r0);

        unsigned acc[NOFF];
        #pragma unroll
        for (int o = 0; o < NOFF; ++o) acc[o] = 0;

        int from = 0;
        #pragma unroll 1
        for (int k = 0; k < NCHUNK; ++k) {
            const int s = k & 1;
            mbar_wait(fu0 + 8u * s, (unsigned)((k >> 1) & 1));

            // pack: warp w packs row 16k + w (16 warps x 1 row)
            {
                const int gr = k * CROWS + warp;
                const float* rp = sbuf + s * CFLOATS + warp * WW;
                unsigned b4[4];
                #pragma unroll
                for (int w = 0; w < WORDS; ++w) {
                    float v = rp[w * 32 + lane];
                    b4[w & 3] = __ballot_sync(0xffffffffu, v > 0.0f);
                    if ((w & 3) == 3 && lane == 0)
                        *reinterpret_cast<uint4*>(&bits[gr * WORDS + (w - 3)])
                            = make_uint4(b4[0], b4[1], b4[2], b4[3]);
                }
            }
            asm volatile("bar.sync 1, %0;" :: "n"(NCONS) : "memory");
            if (tid == 0) mbar_arrive(em0 + 8u * s);   // slot free -> producer

            // count a-rows with complete +3 halo: [from, 16k+13)
            const int to = k * CROWS + CROWS - HALO;
            const int n  = (to - from) * WORDS;
            for (int idx = tid; idx < n; idx += NCONS)
                eval12(bits, from + (idx >> 4), idx & 15, rl, acc);
            from = to;
        }
        // tail rows 125..127 (halo packed at start; ordered by named barriers)
        for (int idx = tid; idx < HALO * WORDS; idx += NCONS)
            eval12(bits, from + (idx >> 4), idx & 15, rl, acc);

        // reduce: warp -> block
        #pragma unroll
        for (int o = 0; o < NOFF; ++o) {
            unsigned v = __reduce_add_sync(0xffffffffu, acc[o]);
            if (lane == 0) {
                atomicAdd(&s_diff[o], (int)(v >> 16));
                atomicAdd(&s_n11[o],  (int)(v & 0xffffu));
            }
        }
    }
    __syncthreads();

    if (tid < NOFF) {
        atomicAdd(&g_cnt[(b * NOFF + tid) * 2 + 0], s_diff[tid]);
        atomicAdd(&g_cnt[(b * NOFF + tid) * 2 + 1], s_n11[tid]);
    }

    // ---- last slab-block of this image finalizes ----------------------------
    if (tid == 0) {
        __threadfence();
        unsigned t = atomicAdd(&g_arrive[b], 1u);
        s_last = (t == SLABS - 1);
    }
    __syncthreads();

    if (s_last && tid < NOFF) {
        const int idx  = b * NOFF + tid;
        const int diff = atomicExch(&g_cnt[idx * 2 + 0], 0);   // read + reset
        const int n11  = atomicExch(&g_cnt[idx * 2 + 1], 0);
        if (tid == 0) atomicExch(&g_arrive[b], 0u);

        const int R  = RS[tid];
        const int Ca = CS[tid] < 0 ? -CS[tid] : CS[tid];
        const int N  = (HH - R) * (WW - Ca);
        const int n00 = N - n11 - diff;

        const float inv = 1.0f / (float)(2 * N - 4 * n00);
        float* o = out + (size_t)b * (NOFF * 4) + tid * 4;
        o[0] = (float)(4 * n00) * inv;
        const float v1 = (float)(2 * diff - 4 * n00) * inv;
        o[1] = v1;
        o[2] = v1;
        o[3] = (float)(2 * (N - 2 * diff)) * inv;
    }
}

extern "C" void kernel_launch(void* const* d_in, const int* in_sizes, int n_in,
                              void* d_out, int out_size)
{
    (void)n_in; (void)out_size;
    const int batch = in_sizes[0] / (HH * WW);           // 128
    const int smem = NSTAGE * CBYTES + BITS_WORDS * 4;   // 65536 + 8448 = 73984
    cudaFuncSetAttribute(glcm_ws, cudaFuncAttributeMaxDynamicSharedMemorySize, smem);
    dim3 grid(SLABS, batch);                             // 4 x 128 = 512 blocks
    glcm_ws<<<grid, NTH, smem>>>((const float*)d_in[0], (float*)d_out);
}

// round 17
// speedup vs baseline: 1.9159x; 1.0967x over previous
#include <cuda_runtime.h>
#include <cstdint>

#define HH 512
#define WW 512
#define WORDS 16
#define SLAB 128
#define HALO 3
#define NTH 512
#define NWARPS 16
#define NOFF 12
#define SLABS (HH / SLAB)
#define MAXB 128
#define BITS_WORDS ((SLAB + HALO) * WORDS + WORDS)   // 2112 incl. guard
#define TROW0 104                        // first TMA-covered row (band 13)
#define TROWSMAX 27                      // rows 104..130
#define TBYTES_ROW (WW * 4)

// zero-initialized; every use paired with a reset -> deterministic graph replays
__device__ int g_cnt[MAXB * NOFF * 2];
__device__ unsigned g_arrive[MAXB];

__device__ __forceinline__ void mbar_init(unsigned a, unsigned cnt) {
    asm volatile("mbarrier.init.shared.b64 [%0], %1;" :: "r"(a), "r"(cnt) : "memory");
}
__device__ __forceinline__ void mbar_expect_tx(unsigned a, unsigned bytes) {
    asm volatile("mbarrier.arrive.expect_tx.shared.b64 _, [%0], %1;"
                 :: "r"(a), "r"(bytes) : "memory");
}
__device__ __forceinline__ void bulk_g2s(unsigned dst, const float* src,
                                         unsigned bytes, unsigned mbar) {
    asm volatile("cp.async.bulk.shared::cluster.global.mbarrier::complete_tx::bytes "
                 "[%0], [%1], %2, [%3];"
                 :: "r"(dst), "l"(src), "r"(bytes), "r"(mbar) : "memory");
}
__device__ __forceinline__ void mbar_wait(unsigned a, unsigned parity) {
    asm volatile(
        "{\n\t"
        ".reg .pred P1;\n\t"
        "WAIT_LOOP_%=:\n\t"
        "mbarrier.try_wait.parity.shared.b64 P1, [%0], %1;\n\t"
        "@P1 bra.uni WAIT_DONE_%=;\n\t"
        "bra.uni WAIT_LOOP_%=;\n\t"
        "WAIT_DONE_%=:\n\t"
        "}"
        :: "r"(a), "r"(parity) : "memory");
}

// evaluate all 12 offsets for bit-word (r, w)
__device__ __forceinline__ void eval12(const unsigned* __restrict__ bits,
                                       int r, int w,
                                       const int* __restrict__ rl,
                                       unsigned* __restrict__ acc)
{
    constexpr int RS[NOFF] = {0, 1, 1, 1, 0, 2, 2, 2, 0, 3, 3, 3};
    constexpr int CS[NOFF] = {1, 1, 0, -1, 2, 2, 0, -2, 3, 3, 0, -3};
    const bool firstw = (w == 0);
    const bool lastw  = (w == WORDS - 1);
    const int i = r * WORDS + w;
    const unsigned A = bits[i];

    #pragma unroll
    for (int o = 0; o < NOFF; ++o) {
        const int R = RS[o];
        const int C = CS[o];
        const int bi = i + R * WORDS;
        unsigned B;
        if (C > 0)       B = __funnelshift_r(bits[bi], bits[bi + 1], C);
        else if (C < 0)  B = __funnelshift_l(bits[bi - 1], bits[bi], -C);
        else             B = bits[bi];

        unsigned m = 0xffffffffu;
        if (C > 0 && lastw)  m = 0xffffffffu >> C;
        if (C < 0 && firstw) m = 0xffffffffu << (-C);
        if (r >= rl[R]) m = 0u;              // last-slab row clip

        acc[o] += (unsigned)(__popc((A ^ B) & m) << 16)
                |  (unsigned)__popc((A & B) & m);
    }
}

// pack one 512-col row (from global or shared) via 16x load+ballot
template<typename PT>
__device__ __forceinline__ void pack_row16(const PT* __restrict__ rp, int lane,
                                           unsigned* __restrict__ dst)
{
    unsigned b4[4];
    #pragma unroll
    for (int w = 0; w < WORDS; ++w) {
        float v = rp[w * 32 + lane];
        b4[w & 3] = __ballot_sync(0xffffffffu, v > 0.0f);
        if ((w & 3) == 3 && lane == 0)
            *reinterpret_cast<uint4*>(&dst[w - 3]) = make_uint4(b4[0], b4[1], b4[2], b4[3]);
    }
}

extern __shared__ unsigned char dynsmem[];

__global__ __launch_bounds__(NTH, 3)
void glcm_hyb(const float* __restrict__ in, float* __restrict__ out)
{
    constexpr int RS[NOFF] = {0, 1, 1, 1, 0, 2, 2, 2, 0, 3, 3, 3};
    constexpr int CS[NOFF] = {1, 1, 0, -1, 2, 2, 0, -2, 3, 3, 0, -3};

    float*    sbuf = reinterpret_cast<float*>(dynsmem);       // 27 rows floats
    unsigned* bits = reinterpret_cast<unsigned*>(dynsmem + TROWSMAX * TBYTES_ROW);
    __shared__ unsigned long long s_mbar;
    __shared__ int s_diff[NOFF];
    __shared__ int s_n11[NOFF];
    __shared__ int s_last;

    const int tid  = threadIdx.x;
    const int lane = tid & 31;
    const int warp = tid >> 5;
    const int r0   = blockIdx.x * SLAB;
    const int b    = blockIdx.y;
    const float* img = in + ((size_t)b * HH + r0) * WW;

    if (tid < NOFF) { s_diff[tid] = 0; s_n11[tid] = 0; }
    if (tid == 0) bits[(SLAB + HALO) * WORDS] = 0u;   // guard word

    const int ntot = min(SLAB + HALO, HH - r0);       // 131 or 128
    const int nt   = ntot - TROW0;                    // 27 or 24 TMA rows
    const unsigned mb = (unsigned)__cvta_generic_to_shared(&s_mbar);

    // ---- warp 13 issues ONE TMA bulk for rows 104..(104+nt) at t=0 ----------
    if (warp == 13) {
        if (lane == 0) mbar_init(mb, 1u);
        asm volatile("bar.sync 1, 96;" ::: "memory");     // warps 13-15: init visible
        if (lane == 0) {
            const unsigned bytes = (unsigned)nt * TBYTES_ROW;
            mbar_expect_tx(mb, bytes);
            bulk_g2s((unsigned)__cvta_generic_to_shared(sbuf),
                     img + TROW0 * WW, bytes, mb);
        }
    } else if (warp > 13) {
        asm volatile("bar.sync 1, 96;" ::: "memory");
    }

    int rl[4];
    #pragma unroll
    for (int R = 0; R < 4; ++R) rl[R] = min(SLAB, HH - R - r0);

    const int base = warp * 8;

    // ---- pack own 8-row band ------------------------------------------------
    if (warp < 13) {
        // LDG path: rows 0..103
        #pragma unroll 2
        for (int j = 0; j < 8; ++j)
            pack_row16(img + (base + j) * WW, lane, &bits[(base + j) * WORDS]);
    } else {
        // TMA path: rows 104..(104+nt) from SMEM
        mbar_wait(mb, 0u);
        for (int j = 0; j < 8; ++j)
            pack_row16(sbuf + (base - TROW0 + j) * WW, lane,
                       &bits[(base + j) * WORDS]);
        // halo row 128+(warp-13), if loaded
        const int hj = 24 + (warp - 13);
        if (hj < nt)
            pack_row16(sbuf + hj * WW, lane, &bits[(TROW0 + hj) * WORDS]);
    }
    __syncwarp();    // order lane0 STS before warp-wide LDS

    // ---- own-band count: a-rows base..base+4 (self-contained) ---------------
    unsigned acc[NOFF];
    #pragma unroll
    for (int o = 0; o < NOFF; ++o) acc[o] = 0;

    for (int e = lane; e < 5 * WORDS; e += 32)
        eval12(bits, base + (e >> 4), e & 15, rl, acc);

    __syncthreads();   // the ONLY block barrier in the hot path

    // ---- deferred boundary rows: r % 8 in {5,6,7}, all bands ----------------
    for (int idx = tid; idx < NWARPS * 3 * WORDS; idx += NTH) {
        const int dr = idx >> 4;            // 0..47
        const int q  = dr / 3;
        const int rr = dr - 3 * q;
        eval12(bits, 8 * q + 5 + rr, idx & 15, rl, acc);
    }

    // ---- reduce: warp -> block -> global -------------------------------------
    #pragma unroll
    for (int o = 0; o < NOFF; ++o) {
        unsigned v = __reduce_add_sync(0xffffffffu, acc[o]);
        if (lane == 0) {
            atomicAdd(&s_diff[o], (int)(v >> 16));
            atomicAdd(&s_n11[o],  (int)(v & 0xffffu));
        }
    }
    __syncthreads();

    if (tid < NOFF) {
        atomicAdd(&g_cnt[(b * NOFF + tid) * 2 + 0], s_diff[tid]);
        atomicAdd(&g_cnt[(b * NOFF + tid) * 2 + 1], s_n11[tid]);
    }

    // ---- last slab-block of this image finalizes -----------------------------
    if (tid == 0) {
        __threadfence();
        unsigned t = atomicAdd(&g_arrive[b], 1u);
        s_last = (t == SLABS - 1);
    }
    __syncthreads();

    if (s_last && tid < NOFF) {
        const int idx  = b * NOFF + tid;
        const int diff = atomicExch(&g_cnt[idx * 2 + 0], 0);   // read + reset
        const int n11  = atomicExch(&g_cnt[idx * 2 + 1], 0);
        if (tid == 0) atomicExch(&g_arrive[b], 0u);

        const int R  = RS[tid];
        const int Ca = CS[tid] < 0 ? -CS[tid] : CS[tid];
        const int N  = (HH - R) * (WW - Ca);
        const int n00 = N - n11 - diff;

        const float inv = 1.0f / (float)(2 * N - 4 * n00);
        float* o = out + (size_t)b * (NOFF * 4) + tid * 4;
        o[0] = (float)(4 * n00) * inv;
        const float v1 = (float)(2 * diff - 4 * n00) * inv;
        o[1] = v1;
        o[2] = v1;
        o[3] = (float)(2 * (N - 2 * diff)) * inv;
    }
}

extern "C" void kernel_launch(void* const* d_in, const int* in_sizes, int n_in,
                              void* d_out, int out_size)
{
    (void)n_in; (void)out_size;
    const int batch = in_sizes[0] / (HH * WW);        // 128
    const int smem = TROWSMAX * TBYTES_ROW + BITS_WORDS * 4;  // 55296+8448=63744
    cudaFuncSetAttribute(glcm_hyb, cudaFuncAttributeMaxDynamicSharedMemorySize, smem);
    dim3 grid(SLABS, batch);                          // 4 x 128 = 512 blocks
    glcm_hyb<<<grid, NTH, smem>>>((const float*)d_in[0], (float*)d_out);
}